// round 14
// baseline (speedup 1.0000x reference)
#include <cuda_runtime.h>
#include <cuda_fp16.h>
#include <math.h>

// Problem constants (fixed by the dataset)
#define NFEAT 128
#define F1    256      // H1*NHID
#define H1    4
#define NHID  64
#define NCLS  16
#define MAXN  50048
#define MAXE  800000
#define EK    96       // fixed bucket stride (max in-degree; Poisson(16) => P(>=96) ~ 1e-40)

#define NEG_SLOPE 0.2f

// ---------------- scratch (static __device__, no allocation) ----------------
__device__ __align__(16) __half g_w1h [NFEAT * F1];    // W1 fp16
__device__ __align__(16) __half g_xw1h[MAXN * F1];     // layer1 x@W1 (fp16)
__device__ __align__(16) __half g_x2h [MAXN * F1];     // layer1 output after ELU (fp16)
__device__ __align__(16) float g_a1s[MAXN * H1];
__device__ __align__(16) float g_a1d[MAXN * H1];
__device__ __align__(16) float g_xw2[MAXN * NCLS];
__device__ float g_a2s[MAXN];
__device__ float g_a2d[MAXN];
__device__ int   g_cnt[MAXN];                  // ZERO at entry (BSS + agg2 re-zeroes)
__device__ int   g_srcs[MAXN * EK];            // src ids, fixed-stride buckets
__device__ int   g_epos[MAXE];                 // prep: rank; sw1e: final slot (or -1)
__device__ __align__(8) uint2 g_w1e[MAXN * EK];// layer1 edge weights, fp16 x4 heads
__device__ float g_w2e[MAXN * EK];             // layer2 edge weights

__device__ __forceinline__ float leaky(float x) {
    return x > 0.f ? x : NEG_SLOPE * x;
}

// ---------------- prep: W1 conversion + histogram with rank capture ----------------
__global__ void prep_kernel(const float* __restrict__ W1,
                            const int* __restrict__ ei, int e, int n) {
    int i = blockIdx.x * blockDim.x + threadIdx.x;
    if (i < NFEAT * F1 / 4) {
        float4 v = *(const float4*)&W1[i * 4];
        __half2* dst = (__half2*)&g_w1h[i * 4];
        dst[0] = __floats2half2_rn(v.x, v.y);
        dst[1] = __floats2half2_rn(v.z, v.w);
    }
    if (i < e) {                       // histogram; atomic return value = rank in bucket
        int d = ei[e + i];
        if (d >= 0 && d < n) {
            g_epos[i] = atomicAdd(&g_cnt[d], 1);
        } else {
            g_epos[i] = -1;
        }
    }
}

// ---------------- GEMM1 (HMMA + ldmatrix) + fused att1; A read fp32 direct ----------------
__global__ void __launch_bounds__(256, 2) gemm1_mma_kernel(
        const float* __restrict__ obs,
        const float* __restrict__ att_s, const float* __restrict__ att_d, int M) {
    __shared__ __half As[128][72];
    __shared__ __half Bs[64][136];
    __shared__ float ps_s[128][4];
    __shared__ float pd_s[128][4];
    const int tid  = threadIdx.x;
    const int wid  = tid >> 5;
    const int lane = tid & 31;
    const int wm = wid >> 2;
    const int wn = wid & 3;
    const int g  = lane >> 2;
    const int t  = lane & 3;
    const int row0 = blockIdx.y * 128;
    const int col0 = blockIdx.x * 128;

    float c[4][4][4];
#pragma unroll
    for (int mt = 0; mt < 4; mt++)
#pragma unroll
        for (int nt = 0; nt < 4; nt++)
#pragma unroll
            for (int q = 0; q < 4; q++) c[mt][nt][q] = 0.f;

    for (int kb = 0; kb < NFEAT; kb += 64) {
        // A tile: 128 rows x 64 k, read fp32 directly, convert to fp16
#pragma unroll
        for (int i = 0; i < 8; i++) {
            int idx = tid + i * 256;          // 2048 float4s
            int r = idx >> 4;                 // 0..127
            int q = idx & 15;                 // float4 within 64 k
            int gr = row0 + r;
            float4 v = make_float4(0.f, 0.f, 0.f, 0.f);
            if (gr < M) v = *(const float4*)&obs[gr * NFEAT + kb + q * 4];
            __half2* dst = (__half2*)&As[r][q * 4];
            dst[0] = __floats2half2_rn(v.x, v.y);
            dst[1] = __floats2half2_rn(v.z, v.w);
        }
        // B tile: 64 k x 128 n, [k][n] layout, coalesced uint2 from fp16 W1
#pragma unroll
        for (int i = 0; i < 8; i++) {
            int idx = tid + i * 256;
            int kr = idx >> 5;
            int nq = idx & 31;
            *(uint2*)&Bs[kr][nq * 4] =
                *(const uint2*)&g_w1h[(kb + kr) * F1 + col0 + nq * 4];
        }
        __syncthreads();
#pragma unroll
        for (int ks = 0; ks < 64; ks += 16) {
            unsigned a[4][4];
#pragma unroll
            for (int mt = 0; mt < 4; mt++) {
                int mr = wm * 64 + mt * 16;
                unsigned addr = (unsigned)__cvta_generic_to_shared(
                    &As[mr + (lane & 15)][ks + 8 * (lane >> 4)]);
                asm volatile(
                    "ldmatrix.sync.aligned.m8n8.x4.shared.b16 {%0,%1,%2,%3}, [%4];"
                    : "=r"(a[mt][0]), "=r"(a[mt][1]), "=r"(a[mt][2]), "=r"(a[mt][3])
                    : "r"(addr));
            }
            unsigned b[4][2];
#pragma unroll
            for (int nt = 0; nt < 4; nt++) {
                int nc = wn * 32 + nt * 8;
                unsigned addr = (unsigned)__cvta_generic_to_shared(
                    &Bs[ks + (lane & 15)][nc]);
                asm volatile(
                    "ldmatrix.sync.aligned.m8n8.x2.trans.shared.b16 {%0,%1}, [%2];"
                    : "=r"(b[nt][0]), "=r"(b[nt][1])
                    : "r"(addr));
            }
#pragma unroll
            for (int mt = 0; mt < 4; mt++)
#pragma unroll
                for (int nt = 0; nt < 4; nt++) {
                    asm volatile(
                        "mma.sync.aligned.m16n8k16.row.col.f32.f16.f16.f32 "
                        "{%0,%1,%2,%3}, {%4,%5,%6,%7}, {%8,%9}, {%0,%1,%2,%3};\n"
                        : "+f"(c[mt][nt][0]), "+f"(c[mt][nt][1]),
                          "+f"(c[mt][nt][2]), "+f"(c[mt][nt][3])
                        : "r"(a[mt][0]), "r"(a[mt][1]), "r"(a[mt][2]), "r"(a[mt][3]),
                          "r"(b[nt][0]), "r"(b[nt][1]));
                }
        }
        __syncthreads();
    }

    float psr[8], pdr[8];
#pragma unroll
    for (int ri = 0; ri < 8; ri++) { psr[ri] = 0.f; pdr[ri] = 0.f; }

#pragma unroll
    for (int mt = 0; mt < 4; mt++) {
#pragma unroll
        for (int nt = 0; nt < 4; nt++) {
            int colg = col0 + wn * 32 + nt * 8 + t * 2;
            float a_s0 = att_s[colg], a_s1 = att_s[colg + 1];
            float a_d0 = att_d[colg], a_d1 = att_d[colg + 1];
            psr[mt*2+0] += c[mt][nt][0] * a_s0 + c[mt][nt][1] * a_s1;
            pdr[mt*2+0] += c[mt][nt][0] * a_d0 + c[mt][nt][1] * a_d1;
            psr[mt*2+1] += c[mt][nt][2] * a_s0 + c[mt][nt][3] * a_s1;
            pdr[mt*2+1] += c[mt][nt][2] * a_d0 + c[mt][nt][3] * a_d1;

            int row = row0 + wm * 64 + mt * 16 + g;
            if (row < M)
                *(__half2*)&g_xw1h[row * F1 + colg] =
                    __floats2half2_rn(c[mt][nt][0], c[mt][nt][1]);
            if (row + 8 < M)
                *(__half2*)&g_xw1h[(row + 8) * F1 + colg] =
                    __floats2half2_rn(c[mt][nt][2], c[mt][nt][3]);
        }
    }
#pragma unroll
    for (int ri = 0; ri < 8; ri++) {
        psr[ri] += __shfl_xor_sync(0xffffffffu, psr[ri], 1);
        psr[ri] += __shfl_xor_sync(0xffffffffu, psr[ri], 2);
        pdr[ri] += __shfl_xor_sync(0xffffffffu, pdr[ri], 1);
        pdr[ri] += __shfl_xor_sync(0xffffffffu, pdr[ri], 2);
    }
    if (t == 0) {
#pragma unroll
        for (int ri = 0; ri < 8; ri++) {
            int row = wm * 64 + (ri >> 1) * 16 + g + (ri & 1) * 8;
            ps_s[row][wn] = psr[ri];
            pd_s[row][wn] = pdr[ri];
        }
    }
    __syncthreads();
    if (tid < 128) {
        int node = row0 + tid;
        if (node < M) {
            int hb = blockIdx.x * 2;
            g_a1s[node * H1 + hb    ] = ps_s[tid][0] + ps_s[tid][1];
            g_a1s[node * H1 + hb + 1] = ps_s[tid][2] + ps_s[tid][3];
            g_a1d[node * H1 + hb    ] = pd_s[tid][0] + pd_s[tid][1];
            g_a1d[node * H1 + hb + 1] = pd_s[tid][2] + pd_s[tid][3];
        }
    }
}

// ---------------- sw1e: fill buckets (src + layer1 weights); no atomics ----------------
__global__ void sw1e_kernel(const int* __restrict__ ei, int e, int n) {
    int i = blockIdx.x * blockDim.x + threadIdx.x;
    if (i < e) {
        int d = ei[e + i];
        int s = ei[i];
        int rank = g_epos[i];
        if (d >= 0 && d < n && s >= 0 && s < n && rank >= 0 && rank < EK) {
            int p = d * EK + rank;
            g_srcs[p] = s;
            g_epos[i] = p;
            float4 as = *(const float4*)&g_a1s[s * H1];
            float4 ad = *(const float4*)&g_a1d[d * H1];
            float w0 = __expf(leaky(as.x + ad.x));
            float w1 = __expf(leaky(as.y + ad.y));
            float w2 = __expf(leaky(as.z + ad.z));
            float w3 = __expf(leaky(as.w + ad.w));
            __half2 h0 = __floats2half2_rn(w0, w1);
            __half2 h1 = __floats2half2_rn(w2, w3);
            uint2 packed;
            packed.x = *(unsigned*)&h0;
            packed.y = *(unsigned*)&h1;
            g_w1e[p] = packed;
        } else {
            g_epos[i] = -1;
        }
    }
}

// ---------------- agg1: 1 warp/node, 8 feats/lane; 2-edge ILP, HFMA2 ----------------
__global__ void agg1_kernel(const float* __restrict__ bias1, int n) {
    int node = (blockIdx.x * blockDim.x + threadIdx.x) >> 5;
    int lane = threadIdx.x & 31;
    if (node >= n) return;

    int fb = lane * 8;                 // 8 contiguous halves per lane
    int head = lane >> 3;
    float adh = g_a1d[node * H1 + head];
    float ash = g_a1s[node * H1 + head];

    int start = node * EK;
    int deg   = g_cnt[node];
    deg = deg < EK ? deg : EK;

    const __half* w1e_h = (const __half*)g_w1e;   // scalar view: slot*4 + head

    float w = __expf(leaky(ash + adh));   // self loop (fp32)
    float sumw = w;
    __half2 acc_a[4], acc_b[4];
    {
        __half2 wh = __float2half2_rn(w);
        uint4 u = *(const uint4*)&g_xw1h[node * F1 + fb];
        acc_a[0] = __hmul2(wh, *(__half2*)&u.x);
        acc_a[1] = __hmul2(wh, *(__half2*)&u.y);
        acc_a[2] = __hmul2(wh, *(__half2*)&u.z);
        acc_a[3] = __hmul2(wh, *(__half2*)&u.w);
        __half2 z = __float2half2_rn(0.f);
        acc_b[0] = z; acc_b[1] = z; acc_b[2] = z; acc_b[3] = z;
    }
    int j = 0;
#pragma unroll 2
    for (; j + 2 <= deg; j += 2) {
        int slot0 = start + j;
        int slot1 = start + j + 1;
        int s0 = g_srcs[slot0];
        int s1 = g_srcs[slot1];
        __half wh0 = w1e_h[slot0 * 4 + head];
        __half wh1 = w1e_h[slot1 * 4 + head];
        uint4 u0 = *(const uint4*)&g_xw1h[s0 * F1 + fb];
        uint4 u1 = *(const uint4*)&g_xw1h[s1 * F1 + fb];
        sumw += __half2float(wh0) + __half2float(wh1);
        __half2 w02 = __half2half2(wh0);
        __half2 w12 = __half2half2(wh1);
        acc_a[0] = __hfma2(w02, *(__half2*)&u0.x, acc_a[0]);
        acc_b[0] = __hfma2(w12, *(__half2*)&u1.x, acc_b[0]);
        acc_a[1] = __hfma2(w02, *(__half2*)&u0.y, acc_a[1]);
        acc_b[1] = __hfma2(w12, *(__half2*)&u1.y, acc_b[1]);
        acc_a[2] = __hfma2(w02, *(__half2*)&u0.z, acc_a[2]);
        acc_b[2] = __hfma2(w12, *(__half2*)&u1.z, acc_b[2]);
        acc_a[3] = __hfma2(w02, *(__half2*)&u0.w, acc_a[3]);
        acc_b[3] = __hfma2(w12, *(__half2*)&u1.w, acc_b[3]);
    }
    if (j < deg) {
        int slot = start + j;
        int s = g_srcs[slot];
        __half whj = w1e_h[slot * 4 + head];
        sumw += __half2float(whj);
        __half2 wj2 = __half2half2(whj);
        uint4 u = *(const uint4*)&g_xw1h[s * F1 + fb];
        acc_a[0] = __hfma2(wj2, *(__half2*)&u.x, acc_a[0]);
        acc_a[1] = __hfma2(wj2, *(__half2*)&u.y, acc_a[1]);
        acc_a[2] = __hfma2(wj2, *(__half2*)&u.z, acc_a[2]);
        acc_a[3] = __hfma2(wj2, *(__half2*)&u.w, acc_a[3]);
    }
    float inv = 1.f / sumw;
    float2 f0 = __half22float2(__hadd2(acc_a[0], acc_b[0]));
    float2 f1 = __half22float2(__hadd2(acc_a[1], acc_b[1]));
    float2 f2 = __half22float2(__hadd2(acc_a[2], acc_b[2]));
    float2 f3 = __half22float2(__hadd2(acc_a[3], acc_b[3]));
    float av[8] = {f0.x, f0.y, f1.x, f1.y, f2.x, f2.y, f3.x, f3.y};
    float o[8];
#pragma unroll
    for (int q = 0; q < 8; q++) {
        float v = av[q] * inv + bias1[fb + q];
        o[q] = v > 0.f ? v : expm1f(v);   // ELU
    }
    __half2* xp = (__half2*)&g_x2h[node * F1 + fb];
    xp[0] = __floats2half2_rn(o[0], o[1]);
    xp[1] = __floats2half2_rn(o[2], o[3]);
    xp[2] = __floats2half2_rn(o[4], o[5]);
    xp[3] = __floats2half2_rn(o[6], o[7]);
}

// ---------------- GEMM2 + fused att2: 256 rows/block ----------------
#define G2_ROWS 256
__global__ void __launch_bounds__(256) gemm2_kernel(
        const float* __restrict__ W2,
        const float* __restrict__ as2, const float* __restrict__ ad2, int n) {
    __shared__ float Xs[G2_ROWS][17];
    __shared__ float ps_sm[G2_ROWS][4];
    __shared__ float pd_sm[G2_ROWS][4];
    const int tid = threadIdx.x;
    const int rowblk = blockIdx.x * G2_ROWS;
    const int rbase = tid & 63;
    const int cg = tid >> 6;
    const int c0 = cg * 4;

    float acc[4][4];
#pragma unroll
    for (int i = 0; i < 4; i++)
#pragma unroll
        for (int j = 0; j < 4; j++) acc[i][j] = 0.f;

    for (int kb = 0; kb < F1; kb += 16) {
#pragma unroll
        for (int i = 0; i < 4; i++) {
            int lr = (tid >> 2) + 64 * i;
            int gr = rowblk + lr;
            int kc = (tid & 3) * 4;
            float2 fa = make_float2(0.f, 0.f), fb = make_float2(0.f, 0.f);
            if (gr < n) {
                uint2 v = *(const uint2*)&g_x2h[gr * F1 + kb + kc];
                fa = __half22float2(*(__half2*)&v.x);
                fb = __half22float2(*(__half2*)&v.y);
            }
            Xs[lr][kc + 0] = fa.x;
            Xs[lr][kc + 1] = fa.y;
            Xs[lr][kc + 2] = fb.x;
            Xs[lr][kc + 3] = fb.y;
        }
        float4 wr[16];
#pragma unroll
        for (int k = 0; k < 16; k++)
            wr[k] = *(const float4*)&W2[(kb + k) * NCLS + c0];
        __syncthreads();
#pragma unroll
        for (int k = 0; k < 16; k++) {
#pragma unroll
            for (int i = 0; i < 4; i++) {
                float xv = Xs[rbase + 64 * i][k];
                acc[i][0] += xv * wr[k].x;
                acc[i][1] += xv * wr[k].y;
                acc[i][2] += xv * wr[k].z;
                acc[i][3] += xv * wr[k].w;
            }
        }
        __syncthreads();
    }
    // store xw2 + partial att2 dots
    float4 sv = *(const float4*)&as2[c0];
    float4 dv = *(const float4*)&ad2[c0];
#pragma unroll
    for (int i = 0; i < 4; i++) {
        int lr = rbase + 64 * i;
        int gr = rowblk + lr;
        if (gr < n)
            *(float4*)&g_xw2[gr * NCLS + c0] =
                make_float4(acc[i][0], acc[i][1], acc[i][2], acc[i][3]);
        ps_sm[lr][cg] = acc[i][0]*sv.x + acc[i][1]*sv.y + acc[i][2]*sv.z + acc[i][3]*sv.w;
        pd_sm[lr][cg] = acc[i][0]*dv.x + acc[i][1]*dv.y + acc[i][2]*dv.z + acc[i][3]*dv.w;
    }
    __syncthreads();
    {
        int gr = rowblk + tid;
        if (tid < G2_ROWS && gr < n) {
            g_a2s[gr] = ps_sm[tid][0] + ps_sm[tid][1] + ps_sm[tid][2] + ps_sm[tid][3];
            g_a2d[gr] = pd_sm[tid][0] + pd_sm[tid][1] + pd_sm[tid][2] + pd_sm[tid][3];
        }
    }
}

// ---------------- w2e: layer2 edge weights (edge-parallel) ----------------
__global__ void w2e_kernel(const int* __restrict__ ei, int e, int n) {
    int i = blockIdx.x * blockDim.x + threadIdx.x;
    if (i < e) {
        int p = g_epos[i];
        if (p >= 0 && p < MAXN * EK) {
            int d = ei[e + i];
            int s = ei[i];
            g_w2e[p] = __expf(leaky(g_a2s[s] + g_a2d[d]));
        }
    }
}

// ---------------- agg2 + final softmax + g_cnt re-zero for next run ----------------
__global__ void agg2_kernel(const float* __restrict__ bias2,
                            float* __restrict__ out, int n) {
    int node = (blockIdx.x * blockDim.x + threadIdx.x) >> 5;
    int lane = threadIdx.x & 31;
    if (node >= n) return;

    int half_ = lane >> 4;
    int c     = lane & 15;
    float sumw = 0.f, acc = 0.f;
    if (half_ == 0) {
        float w = __expf(leaky(g_a2s[node] + g_a2d[node]));
        sumw = w;
        acc  = w * g_xw2[node * NCLS + c];
    }
    int start = node * EK;
    int deg   = g_cnt[node];
    deg = deg < EK ? deg : EK;
#pragma unroll 4
    for (int j = half_; j < deg; j += 2) {
        int s = g_srcs[start + j];
        float wj = g_w2e[start + j];
        sumw += wj;
        acc  += wj * g_xw2[s * NCLS + c];
    }
    sumw += __shfl_xor_sync(0xffffffffu, sumw, 16);
    acc  += __shfl_xor_sync(0xffffffffu, acc, 16);

    float logit = acc / sumw + bias2[c];

    float mx = logit;
#pragma unroll
    for (int off = 8; off > 0; off >>= 1)
        mx = fmaxf(mx, __shfl_xor_sync(0xffffffffu, mx, off));
    float p = __expf(logit - mx);
    float s16 = p;
#pragma unroll
    for (int off = 8; off > 0; off >>= 1)
        s16 += __shfl_xor_sync(0xffffffffu, s16, off);
    if (lane < NCLS) out[node * NCLS + lane] = p / s16;

    // re-zero this node's degree for the next run (deg already read above)
    if (lane == 0) g_cnt[node] = 0;
}

// ---------------- launch ----------------
extern "C" void kernel_launch(void* const* d_in, const int* in_sizes, int n_in,
                              void* d_out, int out_size) {
    const float* obs  = (const float*)d_in[0];
    const int*   ei   = (const int*)d_in[1];   // int32 (confirmed: int64 read crashes)
    const float* W1   = (const float*)d_in[2];
    const float* as1  = (const float*)d_in[3];
    const float* ad1  = (const float*)d_in[4];
    const float* b1   = (const float*)d_in[5];
    const float* W2   = (const float*)d_in[6];
    const float* as2  = (const float*)d_in[7];
    const float* ad2  = (const float*)d_in[8];
    const float* b2   = (const float*)d_in[9];
    float* out = (float*)d_out;

    int n = in_sizes[0] / NFEAT;
    int e = in_sizes[1] / 2;

    prep_kernel<<<(e + 255) / 256, 256>>>(W1, ei, e, n);                         // 0
    gemm1_mma_kernel<<<dim3(F1 / 128, (n + 127) / 128), 256>>>(obs, as1, ad1, n);// 1
    sw1e_kernel<<<(e + 255) / 256, 256>>>(ei, e, n);                             // 2
    agg1_kernel<<<(n + 7) / 8, 256>>>(b1, n);                                    // 3 (ncu slot)
    gemm2_kernel<<<(n + G2_ROWS - 1) / G2_ROWS, 256>>>(W2, as2, ad2, n);         // 4
    w2e_kernel<<<(e + 255) / 256, 256>>>(ei, e, n);                              // 5
    agg2_kernel<<<(n + 7) / 8, 256>>>(b2, out, n);                               // 6
}

// round 15
// speedup vs baseline: 1.0304x; 1.0304x over previous
#include <cuda_runtime.h>
#include <cuda_fp16.h>
#include <math.h>

// Problem constants (fixed by the dataset)
#define NFEAT 128
#define F1    256      // H1*NHID
#define H1    4
#define NHID  64
#define NCLS  16
#define MAXN  50048
#define MAXE  800000
#define EK    96       // fixed bucket stride (max in-degree; Poisson(16) => P(>=96) ~ 1e-40)

#define NEG_SLOPE 0.2f

// ---------------- scratch (static __device__, no allocation) ----------------
__device__ __align__(16) __half g_obsh[MAXN * NFEAT];  // obs fp16 (tail rows stay 0)
__device__ __align__(16) __half g_w1h [NFEAT * F1];    // W1 fp16
__device__ __align__(16) __half g_xw1h[MAXN * F1];     // layer1 x@W1 (fp16)
__device__ __align__(16) __half g_x2h [MAXN * F1];     // layer1 output after ELU (fp16)
__device__ __align__(16) float g_a1s[MAXN * H1];
__device__ __align__(16) float g_a1d[MAXN * H1];
__device__ __align__(16) float g_xw2[MAXN * NCLS];
__device__ float g_a2s[MAXN];
__device__ float g_a2d[MAXN];
__device__ int   g_cnt[MAXN];                  // ZERO at entry (BSS + agg2 re-zeroes)
__device__ int   g_srcs[MAXN * EK];            // src ids, fixed-stride buckets
__device__ int   g_epos[MAXE];                 // prep: rank; sw1e: final slot (or -1)
__device__ __align__(8) uint2 g_w1e[MAXN * EK];// layer1 edge weights, fp16 x4 heads
__device__ float g_w2e[MAXN * EK];             // layer2 edge weights

__device__ __forceinline__ float leaky(float x) {
    return x > 0.f ? x : NEG_SLOPE * x;
}

// ---------------- prep: conversions + histogram with rank capture ----------------
__global__ void prep_kernel(const float* __restrict__ obs,
                            const float* __restrict__ W1,
                            const int* __restrict__ ei, int e, int n, int m4) {
    int i = blockIdx.x * blockDim.x + threadIdx.x;
    if (i < m4) {
        float4 v = *(const float4*)&obs[i * 4];
        __half2* dst = (__half2*)&g_obsh[i * 4];
        dst[0] = __floats2half2_rn(v.x, v.y);
        dst[1] = __floats2half2_rn(v.z, v.w);
    }
    if (i < NFEAT * F1 / 4) {
        float4 v = *(const float4*)&W1[i * 4];
        __half2* dst = (__half2*)&g_w1h[i * 4];
        dst[0] = __floats2half2_rn(v.x, v.y);
        dst[1] = __floats2half2_rn(v.z, v.w);
    }
    if (i < e) {                       // histogram; atomic return value = rank in bucket
        int d = ei[e + i];
        if (d >= 0 && d < n) {
            g_epos[i] = atomicAdd(&g_cnt[d], 1);
        } else {
            g_epos[i] = -1;
        }
    }
}

// ---------------- GEMM1 (HMMA + ldmatrix) + fused att1 ----------------
__global__ void __launch_bounds__(256, 2) gemm1_mma_kernel(
        const float* __restrict__ att_s, const float* __restrict__ att_d, int M) {
    __shared__ __half As[128][72];
    __shared__ __half Bs[64][136];
    __shared__ float ps_s[128][4];
    __shared__ float pd_s[128][4];
    const int tid  = threadIdx.x;
    const int wid  = tid >> 5;
    const int lane = tid & 31;
    const int wm = wid >> 2;
    const int wn = wid & 3;
    const int g  = lane >> 2;
    const int t  = lane & 3;
    const int row0 = blockIdx.y * 128;
    const int col0 = blockIdx.x * 128;

    float c[4][4][4];
#pragma unroll
    for (int mt = 0; mt < 4; mt++)
#pragma unroll
        for (int nt = 0; nt < 4; nt++)
#pragma unroll
            for (int q = 0; q < 4; q++) c[mt][nt][q] = 0.f;

    for (int kb = 0; kb < NFEAT; kb += 64) {
#pragma unroll
        for (int i = 0; i < 8; i++) {
            int idx = tid + i * 256;
            int r = idx >> 4;
            int q = idx & 15;
            *(uint2*)&As[r][q * 4] =
                *(const uint2*)&g_obsh[(row0 + r) * NFEAT + kb + q * 4];
        }
#pragma unroll
        for (int i = 0; i < 8; i++) {
            int idx = tid + i * 256;
            int kr = idx >> 5;
            int nq = idx & 31;
            *(uint2*)&Bs[kr][nq * 4] =
                *(const uint2*)&g_w1h[(kb + kr) * F1 + col0 + nq * 4];
        }
        __syncthreads();
#pragma unroll
        for (int ks = 0; ks < 64; ks += 16) {
            unsigned a[4][4];
#pragma unroll
            for (int mt = 0; mt < 4; mt++) {
                int mr = wm * 64 + mt * 16;
                unsigned addr = (unsigned)__cvta_generic_to_shared(
                    &As[mr + (lane & 15)][ks + 8 * (lane >> 4)]);
                asm volatile(
                    "ldmatrix.sync.aligned.m8n8.x4.shared.b16 {%0,%1,%2,%3}, [%4];"
                    : "=r"(a[mt][0]), "=r"(a[mt][1]), "=r"(a[mt][2]), "=r"(a[mt][3])
                    : "r"(addr));
            }
            unsigned b[4][2];
#pragma unroll
            for (int nt = 0; nt < 4; nt++) {
                int nc = wn * 32 + nt * 8;
                unsigned addr = (unsigned)__cvta_generic_to_shared(
                    &Bs[ks + (lane & 15)][nc]);
                asm volatile(
                    "ldmatrix.sync.aligned.m8n8.x2.trans.shared.b16 {%0,%1}, [%2];"
                    : "=r"(b[nt][0]), "=r"(b[nt][1])
                    : "r"(addr));
            }
#pragma unroll
            for (int mt = 0; mt < 4; mt++)
#pragma unroll
                for (int nt = 0; nt < 4; nt++) {
                    asm volatile(
                        "mma.sync.aligned.m16n8k16.row.col.f32.f16.f16.f32 "
                        "{%0,%1,%2,%3}, {%4,%5,%6,%7}, {%8,%9}, {%0,%1,%2,%3};\n"
                        : "+f"(c[mt][nt][0]), "+f"(c[mt][nt][1]),
                          "+f"(c[mt][nt][2]), "+f"(c[mt][nt][3])
                        : "r"(a[mt][0]), "r"(a[mt][1]), "r"(a[mt][2]), "r"(a[mt][3]),
                          "r"(b[nt][0]), "r"(b[nt][1]));
                }
        }
        __syncthreads();
    }

    float psr[8], pdr[8];
#pragma unroll
    for (int ri = 0; ri < 8; ri++) { psr[ri] = 0.f; pdr[ri] = 0.f; }

#pragma unroll
    for (int mt = 0; mt < 4; mt++) {
#pragma unroll
        for (int nt = 0; nt < 4; nt++) {
            int colg = col0 + wn * 32 + nt * 8 + t * 2;
            float a_s0 = att_s[colg], a_s1 = att_s[colg + 1];
            float a_d0 = att_d[colg], a_d1 = att_d[colg + 1];
            psr[mt*2+0] += c[mt][nt][0] * a_s0 + c[mt][nt][1] * a_s1;
            pdr[mt*2+0] += c[mt][nt][0] * a_d0 + c[mt][nt][1] * a_d1;
            psr[mt*2+1] += c[mt][nt][2] * a_s0 + c[mt][nt][3] * a_s1;
            pdr[mt*2+1] += c[mt][nt][2] * a_d0 + c[mt][nt][3] * a_d1;

            int row = row0 + wm * 64 + mt * 16 + g;
            if (row < M)
                *(__half2*)&g_xw1h[row * F1 + colg] =
                    __floats2half2_rn(c[mt][nt][0], c[mt][nt][1]);
            if (row + 8 < M)
                *(__half2*)&g_xw1h[(row + 8) * F1 + colg] =
                    __floats2half2_rn(c[mt][nt][2], c[mt][nt][3]);
        }
    }
#pragma unroll
    for (int ri = 0; ri < 8; ri++) {
        psr[ri] += __shfl_xor_sync(0xffffffffu, psr[ri], 1);
        psr[ri] += __shfl_xor_sync(0xffffffffu, psr[ri], 2);
        pdr[ri] += __shfl_xor_sync(0xffffffffu, pdr[ri], 1);
        pdr[ri] += __shfl_xor_sync(0xffffffffu, pdr[ri], 2);
    }
    if (t == 0) {
#pragma unroll
        for (int ri = 0; ri < 8; ri++) {
            int row = wm * 64 + (ri >> 1) * 16 + g + (ri & 1) * 8;
            ps_s[row][wn] = psr[ri];
            pd_s[row][wn] = pdr[ri];
        }
    }
    __syncthreads();
    if (tid < 128) {
        int node = row0 + tid;
        if (node < M) {
            int hb = blockIdx.x * 2;
            g_a1s[node * H1 + hb    ] = ps_s[tid][0] + ps_s[tid][1];
            g_a1s[node * H1 + hb + 1] = ps_s[tid][2] + ps_s[tid][3];
            g_a1d[node * H1 + hb    ] = pd_s[tid][0] + pd_s[tid][1];
            g_a1d[node * H1 + hb + 1] = pd_s[tid][2] + pd_s[tid][3];
        }
    }
}

// ---------------- sw1e: fill buckets (src + layer1 weights); no atomics ----------------
__global__ void sw1e_kernel(const int* __restrict__ ei, int e, int n) {
    int i = blockIdx.x * blockDim.x + threadIdx.x;
    if (i < e) {
        int d = ei[e + i];
        int s = ei[i];
        int rank = g_epos[i];
        if (d >= 0 && d < n && s >= 0 && s < n && rank >= 0 && rank < EK) {
            int p = d * EK + rank;
            g_srcs[p] = s;
            g_epos[i] = p;
            float4 as = *(const float4*)&g_a1s[s * H1];
            float4 ad = *(const float4*)&g_a1d[d * H1];
            float w0 = __expf(leaky(as.x + ad.x));
            float w1 = __expf(leaky(as.y + ad.y));
            float w2 = __expf(leaky(as.z + ad.z));
            float w3 = __expf(leaky(as.w + ad.w));
            __half2 h0 = __floats2half2_rn(w0, w1);
            __half2 h1 = __floats2half2_rn(w2, w3);
            uint2 packed;
            packed.x = *(unsigned*)&h0;
            packed.y = *(unsigned*)&h1;
            g_w1e[p] = packed;
        } else {
            g_epos[i] = -1;
        }
    }
}

// ---------------- agg1: 1 warp/node, 8 feats/lane; 2-edge ILP, HFMA2, fast ELU ----------------
__global__ void agg1_kernel(const float* __restrict__ bias1, int n) {
    int node = (blockIdx.x * blockDim.x + threadIdx.x) >> 5;
    int lane = threadIdx.x & 31;
    if (node >= n) return;

    int fb = lane * 8;                 // 8 contiguous halves per lane
    int head = lane >> 3;
    float adh = g_a1d[node * H1 + head];
    float ash = g_a1s[node * H1 + head];

    int start = node * EK;
    int deg   = g_cnt[node];
    deg = deg < EK ? deg : EK;

    const __half* w1e_h = (const __half*)g_w1e;   // scalar view: slot*4 + head

    float w = __expf(leaky(ash + adh));   // self loop (fp32)
    float sumw = w;
    __half2 acc_a[4], acc_b[4];
    {
        __half2 wh = __float2half2_rn(w);
        uint4 u = *(const uint4*)&g_xw1h[node * F1 + fb];
        acc_a[0] = __hmul2(wh, *(__half2*)&u.x);
        acc_a[1] = __hmul2(wh, *(__half2*)&u.y);
        acc_a[2] = __hmul2(wh, *(__half2*)&u.z);
        acc_a[3] = __hmul2(wh, *(__half2*)&u.w);
        __half2 z = __float2half2_rn(0.f);
        acc_b[0] = z; acc_b[1] = z; acc_b[2] = z; acc_b[3] = z;
    }
    int j = 0;
#pragma unroll 2
    for (; j + 2 <= deg; j += 2) {
        int slot0 = start + j;
        int slot1 = start + j + 1;
        int s0 = g_srcs[slot0];
        int s1 = g_srcs[slot1];
        __half wh0 = w1e_h[slot0 * 4 + head];
        __half wh1 = w1e_h[slot1 * 4 + head];
        uint4 u0 = *(const uint4*)&g_xw1h[s0 * F1 + fb];
        uint4 u1 = *(const uint4*)&g_xw1h[s1 * F1 + fb];
        sumw += __half2float(wh0) + __half2float(wh1);
        __half2 w02 = __half2half2(wh0);
        __half2 w12 = __half2half2(wh1);
        acc_a[0] = __hfma2(w02, *(__half2*)&u0.x, acc_a[0]);
        acc_b[0] = __hfma2(w12, *(__half2*)&u1.x, acc_b[0]);
        acc_a[1] = __hfma2(w02, *(__half2*)&u0.y, acc_a[1]);
        acc_b[1] = __hfma2(w12, *(__half2*)&u1.y, acc_b[1]);
        acc_a[2] = __hfma2(w02, *(__half2*)&u0.z, acc_a[2]);
        acc_b[2] = __hfma2(w12, *(__half2*)&u1.z, acc_b[2]);
        acc_a[3] = __hfma2(w02, *(__half2*)&u0.w, acc_a[3]);
        acc_b[3] = __hfma2(w12, *(__half2*)&u1.w, acc_b[3]);
    }
    if (j < deg) {
        int slot = start + j;
        int s = g_srcs[slot];
        __half whj = w1e_h[slot * 4 + head];
        sumw += __half2float(whj);
        __half2 wj2 = __half2half2(whj);
        uint4 u = *(const uint4*)&g_xw1h[s * F1 + fb];
        acc_a[0] = __hfma2(wj2, *(__half2*)&u.x, acc_a[0]);
        acc_a[1] = __hfma2(wj2, *(__half2*)&u.y, acc_a[1]);
        acc_a[2] = __hfma2(wj2, *(__half2*)&u.z, acc_a[2]);
        acc_a[3] = __hfma2(wj2, *(__half2*)&u.w, acc_a[3]);
    }
    float inv = 1.f / sumw;
    float2 f0 = __half22float2(__hadd2(acc_a[0], acc_b[0]));
    float2 f1 = __half22float2(__hadd2(acc_a[1], acc_b[1]));
    float2 f2 = __half22float2(__hadd2(acc_a[2], acc_b[2]));
    float2 f3 = __half22float2(__hadd2(acc_a[3], acc_b[3]));
    float av[8] = {f0.x, f0.y, f1.x, f1.y, f2.x, f2.y, f3.x, f3.y};
    float o[8];
#pragma unroll
    for (int q = 0; q < 8; q++) {
        float v = av[q] * inv + bias1[fb + q];
        o[q] = v > 0.f ? v : (__expf(v) - 1.f);   // fast ELU (HW ex2)
    }
    __half2* xp = (__half2*)&g_x2h[node * F1 + fb];
    xp[0] = __floats2half2_rn(o[0], o[1]);
    xp[1] = __floats2half2_rn(o[2], o[3]);
    xp[2] = __floats2half2_rn(o[4], o[5]);
    xp[3] = __floats2half2_rn(o[6], o[7]);
}

// ---------------- GEMM2 + fused att2: 256 rows/block ----------------
#define G2_ROWS 256
__global__ void __launch_bounds__(256) gemm2_kernel(
        const float* __restrict__ W2,
        const float* __restrict__ as2, const float* __restrict__ ad2, int n) {
    __shared__ float Xs[G2_ROWS][17];
    __shared__ float ps_sm[G2_ROWS][4];
    __shared__ float pd_sm[G2_ROWS][4];
    const int tid = threadIdx.x;
    const int rowblk = blockIdx.x * G2_ROWS;
    const int rbase = tid & 63;
    const int cg = tid >> 6;
    const int c0 = cg * 4;

    float acc[4][4];
#pragma unroll
    for (int i = 0; i < 4; i++)
#pragma unroll
        for (int j = 0; j < 4; j++) acc[i][j] = 0.f;

    for (int kb = 0; kb < F1; kb += 16) {
#pragma unroll
        for (int i = 0; i < 4; i++) {
            int lr = (tid >> 2) + 64 * i;
            int gr = rowblk + lr;
            int kc = (tid & 3) * 4;
            float2 fa = make_float2(0.f, 0.f), fb = make_float2(0.f, 0.f);
            if (gr < n) {
                uint2 v = *(const uint2*)&g_x2h[gr * F1 + kb + kc];
                fa = __half22float2(*(__half2*)&v.x);
                fb = __half22float2(*(__half2*)&v.y);
            }
            Xs[lr][kc + 0] = fa.x;
            Xs[lr][kc + 1] = fa.y;
            Xs[lr][kc + 2] = fb.x;
            Xs[lr][kc + 3] = fb.y;
        }
        float4 wr[16];
#pragma unroll
        for (int k = 0; k < 16; k++)
            wr[k] = *(const float4*)&W2[(kb + k) * NCLS + c0];
        __syncthreads();
#pragma unroll
        for (int k = 0; k < 16; k++) {
#pragma unroll
            for (int i = 0; i < 4; i++) {
                float xv = Xs[rbase + 64 * i][k];
                acc[i][0] += xv * wr[k].x;
                acc[i][1] += xv * wr[k].y;
                acc[i][2] += xv * wr[k].z;
                acc[i][3] += xv * wr[k].w;
            }
        }
        __syncthreads();
    }
    // store xw2 + partial att2 dots
    float4 sv = *(const float4*)&as2[c0];
    float4 dv = *(const float4*)&ad2[c0];
#pragma unroll
    for (int i = 0; i < 4; i++) {
        int lr = rbase + 64 * i;
        int gr = rowblk + lr;
        if (gr < n)
            *(float4*)&g_xw2[gr * NCLS + c0] =
                make_float4(acc[i][0], acc[i][1], acc[i][2], acc[i][3]);
        ps_sm[lr][cg] = acc[i][0]*sv.x + acc[i][1]*sv.y + acc[i][2]*sv.z + acc[i][3]*sv.w;
        pd_sm[lr][cg] = acc[i][0]*dv.x + acc[i][1]*dv.y + acc[i][2]*dv.z + acc[i][3]*dv.w;
    }
    __syncthreads();
    {
        int gr = rowblk + tid;
        if (tid < G2_ROWS && gr < n) {
            g_a2s[gr] = ps_sm[tid][0] + ps_sm[tid][1] + ps_sm[tid][2] + ps_sm[tid][3];
            g_a2d[gr] = pd_sm[tid][0] + pd_sm[tid][1] + pd_sm[tid][2] + pd_sm[tid][3];
        }
    }
}

// ---------------- w2e: layer2 edge weights (edge-parallel) ----------------
__global__ void w2e_kernel(const int* __restrict__ ei, int e, int n) {
    int i = blockIdx.x * blockDim.x + threadIdx.x;
    if (i < e) {
        int p = g_epos[i];
        if (p >= 0 && p < MAXN * EK) {
            int d = ei[e + i];
            int s = ei[i];
            g_w2e[p] = __expf(leaky(g_a2s[s] + g_a2d[d]));
        }
    }
}

// ---------------- agg2 + final softmax + g_cnt re-zero for next run ----------------
__global__ void agg2_kernel(const float* __restrict__ bias2,
                            float* __restrict__ out, int n) {
    int node = (blockIdx.x * blockDim.x + threadIdx.x) >> 5;
    int lane = threadIdx.x & 31;
    if (node >= n) return;

    int half_ = lane >> 4;
    int c     = lane & 15;
    float sumw = 0.f, acc = 0.f;
    if (half_ == 0) {
        float w = __expf(leaky(g_a2s[node] + g_a2d[node]));
        sumw = w;
        acc  = w * g_xw2[node * NCLS + c];
    }
    int start = node * EK;
    int deg   = g_cnt[node];
    deg = deg < EK ? deg : EK;
#pragma unroll 4
    for (int j = half_; j < deg; j += 2) {
        int s = g_srcs[start + j];
        float wj = g_w2e[start + j];
        sumw += wj;
        acc  += wj * g_xw2[s * NCLS + c];
    }
    sumw += __shfl_xor_sync(0xffffffffu, sumw, 16);
    acc  += __shfl_xor_sync(0xffffffffu, acc, 16);

    float logit = acc / sumw + bias2[c];

    float mx = logit;
#pragma unroll
    for (int off = 8; off > 0; off >>= 1)
        mx = fmaxf(mx, __shfl_xor_sync(0xffffffffu, mx, off));
    float p = __expf(logit - mx);
    float s16 = p;
#pragma unroll
    for (int off = 8; off > 0; off >>= 1)
        s16 += __shfl_xor_sync(0xffffffffu, s16, off);
    if (lane < NCLS) out[node * NCLS + lane] = p / s16;

    // re-zero this node's degree for the next run (deg already read above)
    if (lane == 0) g_cnt[node] = 0;
}

// ---------------- launch ----------------
extern "C" void kernel_launch(void* const* d_in, const int* in_sizes, int n_in,
                              void* d_out, int out_size) {
    const float* obs  = (const float*)d_in[0];
    const int*   ei   = (const int*)d_in[1];   // int32 (confirmed: int64 read crashes)
    const float* W1   = (const float*)d_in[2];
    const float* as1  = (const float*)d_in[3];
    const float* ad1  = (const float*)d_in[4];
    const float* b1   = (const float*)d_in[5];
    const float* W2   = (const float*)d_in[6];
    const float* as2  = (const float*)d_in[7];
    const float* ad2  = (const float*)d_in[8];
    const float* b2   = (const float*)d_in[9];
    float* out = (float*)d_out;

    int n = in_sizes[0] / NFEAT;
    int e = in_sizes[1] / 2;
    int m4 = n * NFEAT / 4;
    int prep_threads = m4 > e ? m4 : e;

    prep_kernel<<<(prep_threads + 255) / 256, 256>>>(obs, W1, ei, e, n, m4); // 0
    gemm1_mma_kernel<<<dim3(F1 / 128, (n + 127) / 128), 256>>>(as1, ad1, n); // 1
    sw1e_kernel<<<(e + 255) / 256, 256>>>(ei, e, n);                         // 2
    agg1_kernel<<<(n + 7) / 8, 256>>>(b1, n);                                // 3 (ncu slot)
    gemm2_kernel<<<(n + G2_ROWS - 1) / G2_ROWS, 256>>>(W2, as2, ad2, n);     // 4
    w2e_kernel<<<(e + 255) / 256, 256>>>(ei, e, n);                          // 5
    agg2_kernel<<<(n + 7) / 8, 256>>>(b2, out, n);                           // 6
}